// round 13
// baseline (speedup 1.0000x reference)
#include <cuda_runtime.h>

constexpr int H = 256, W = 256, PLANES = 12;
constexpr int HH = 1024, WH = 1024;
constexpr float EPSF  = 1e-8f;
constexpr float EPSSF = 1e-12f;
constexpr int PSZ = PLANES * H * W;

constexpr int PRP = 49;   // halo pitch (48 + 1)
constexpr int HSP = 33;   // hsum pitch (32 + 1)

__device__ float  g_partial[768];
__device__ float2 g_ab [PSZ];    // interleaved (A, b)
__device__ float2 g_mab[PSZ];    // interleaved (meanA, meanb)

__device__ __forceinline__ void gdc_wait()    { asm volatile("griddepcontrol.wait;" ::: "memory"); }
__device__ __forceinline__ void gdc_trigger() { asm volatile("griddepcontrol.launch_dependents;" ::: "memory"); }

// ---------- K1: partial sums of |l_a|+eps ----------
__global__ void k_reduce1(const float* __restrict__ la) {
    __shared__ float sm[256];
    gdc_trigger();                    // let box1 stage its halo concurrently
    int t = threadIdx.x;
    float4 v = ((const float4*)la)[blockIdx.x * 256 + t];
    float s = fabsf(v.x) + fabsf(v.y) + fabsf(v.z) + fabsf(v.w) + 4.0f * EPSSF;
    sm[t] = s; __syncthreads();
    for (int off = 128; off > 0; off >>= 1) {
        if (t < off) sm[t] += sm[t + off];
        __syncthreads();
    }
    if (t == 0) g_partial[blockIdx.x] = sm[0];
}

// ---------- K2: box filter #1 + A,b (PDL: halo staged pre-wait) ----------
constexpr int B1_AXY = 3 * 48 * PRP;            // 7056 floats
constexpr int B1_FL  = B1_AXY + 6 * 48 * HSP;   // 16560 floats (66240 B)

__device__ __forceinline__ void acc_prod(float* s, float a, float x, float y,
                                         float sign) {
    float ax  = a * x;
    float a2x = ax * a;
    s[0] += sign * a;
    s[1] += sign * a2x * y;
    s[2] += sign * a2x;
    s[3] += sign * a * y;
    s[4] += sign * ax * ax;
    s[5] += sign * ax;
}

__global__ __launch_bounds__(384)
void k_box1(const float* __restrict__ lx,
            const float* __restrict__ ly,
            const float* __restrict__ la) {
    extern __shared__ float smd[];
    float* sa = smd;
    float* sx = smd + 48 * PRP;
    float* sy = smd + 2 * 48 * PRP;
    float* hs = smd + B1_AXY;        // [6][48][HSP]
    __shared__ float sred[256];
    __shared__ float s_inv;

    int t = threadIdx.x;
    int plane = blockIdx.x >> 6, tile = blockIdx.x & 63;
    int R0 = (tile >> 3) * 32;
    int C0 = (tile & 7) * 32;
    int pbase = plane * H * W;

    gdc_trigger();                    // let box2 launch early (it waits on us)

    // phase 1 (pre-wait): stage 48x48 halo of a,x,y — independent of reduce1
    for (int i = t; i < 48 * 48; i += 384) {
        int lr = i / 48, lc = i - lr * 48;
        int gr = R0 - 8 + lr, gc = C0 - 8 + lc;
        float a = 0.f, x = 0.f, y = 0.f;
        if (gr >= 0 && gr < H && gc >= 0 && gc < W) {
            int idx = pbase + gr * W + gc;
            a = fabsf(la[idx]) + EPSSF;
            x = lx[idx];
            y = ly[idx];
        }
        int o = lr * PRP + lc;
        sa[o] = a; sx[o] = x; sy[o] = y;
    }

    gdc_wait();                       // reduce1's g_partial now visible

    if (t < 256)
        sred[t] = g_partial[t] + g_partial[t + 256] + g_partial[t + 512];
    __syncthreads();
    for (int off = 128; off > 0; off >>= 1) {
        if (t < off) sred[t] += sred[t + off];
        __syncthreads();
    }
    if (t == 0) s_inv = __fdividef(1.0f, sred[0]);
    __syncthreads();

    // phase 2: H-box with on-the-fly products. 384 jobs, 1 per thread.
    {
        int r = t >> 3, sg = t & 7;
        int base = r * PRP + sg * 4;
        float s[6] = {0,0,0,0,0,0};
#pragma unroll
        for (int k = 0; k < 17; k++)
            acc_prod(s, sa[base + k], sx[base + k], sy[base + k], 1.0f);
        int ho = r * HSP + sg * 4;
#pragma unroll
        for (int c = 0; c < 6; c++) hs[c * 48 * HSP + ho] = s[c];
#pragma unroll
        for (int i = 1; i < 4; i++) {
            int add = base + 16 + i, sub = base + i - 1;
            acc_prod(s, sa[add], sx[add], sy[add], 1.0f);
            acc_prod(s, sa[sub], sx[sub], sy[sub], -1.0f);
#pragma unroll
            for (int c = 0; c < 6; c++) hs[c * 48 * HSP + ho + i] = s[c];
        }
    }
    __syncthreads();

    // phase 3: V-box + A,b. 256 jobs (t < 256).
    if (t < 256) {
        float invS = s_inv;
        int col = t & 31, seg = t >> 5;
        int rl0 = seg * 4;
        float s[6] = {0,0,0,0,0,0};
#pragma unroll
        for (int k = 0; k < 17; k++) {
#pragma unroll
            for (int c = 0; c < 6; c++)
                s[c] += hs[(c * 48 + rl0 + k) * HSP + col];
        }
        int oc = C0 + col;
        int nx = min(W - 1, oc + 8) - max(0, oc - 8) + 1;

#pragma unroll
        for (int i = 0; i < 4; i++) {
            if (i > 0) {
#pragma unroll
                for (int c = 0; c < 6; c++)
                    s[c] += hs[(c * 48 + rl0 + 16 + i) * HSP + col]
                          - hs[(c * 48 + rl0 + i - 1) * HSP + col];
            }
            int orow = R0 + rl0 + i;
            int ny = min(H - 1, orow + 8) - max(0, orow - 8) + 1;
            float Nf = (float)(nx * ny);
            float invN = __fdividef(1.0f, Nf);

            float m_a    = s[0] * invN;
            float m_a2xy = s[1] * invN;
            float m_tax  = invS * s[2] * invN;
            float m_ay   = s[3] * invN;
            float m_a2x2 = s[4] * invN;
            float m_ax   = s[5] * invN;

            float temp = fabsf(m_a2x2 - Nf * m_tax * m_ax);
            float A = __fdividef(m_a2xy - Nf * m_tax * m_ay, temp + EPSF);
            float b = __fdividef(m_ay - A * m_ax, m_a);

            g_ab[pbase + orow * W + oc] = make_float2(A, b);
        }
    }
}

// ---------- K3: box filter #2 (PDL both sides) ----------
__global__ __launch_bounds__(384)
void k_box2() {
    __shared__ float ab [2 * 48 * PRP];
    __shared__ float hs2[2 * 48 * HSP];
    gdc_trigger();                    // let k_up front-load hr concurrently
    int t = threadIdx.x;
    int plane = blockIdx.x >> 6, tile = blockIdx.x & 63;
    int R0 = (tile >> 3) * 32;
    int C0 = (tile & 7) * 32;
    int pbase = plane * H * W;

    gdc_wait();                       // box1's g_ab now visible

    for (int i = t; i < 48 * 48; i += 384) {
        int lr = i / 48, lc = i - lr * 48;
        int gr = R0 - 8 + lr, gc = C0 - 8 + lc;
        float2 v = make_float2(0.f, 0.f);
        if (gr >= 0 && gr < H && gc >= 0 && gc < W)
            v = g_ab[pbase + gr * W + gc];
        ab[(0 * 48 + lr) * PRP + lc] = v.x;
        ab[(1 * 48 + lr) * PRP + lc] = v.y;
    }
    __syncthreads();

    {
        int r = t >> 3, sgc = t & 7;
        int lc0 = sgc * 4;
        float sav = 0.f, sbv = 0.f;
#pragma unroll
        for (int k = 0; k < 17; k++) {
            sav += ab[(0 * 48 + r) * PRP + lc0 + k];
            sbv += ab[(1 * 48 + r) * PRP + lc0 + k];
        }
        hs2[(0 * 48 + r) * HSP + lc0] = sav;
        hs2[(1 * 48 + r) * HSP + lc0] = sbv;
#pragma unroll
        for (int i = 1; i < 4; i++) {
            sav += ab[(0 * 48 + r) * PRP + lc0 + 16 + i]
                 - ab[(0 * 48 + r) * PRP + lc0 + i - 1];
            sbv += ab[(1 * 48 + r) * PRP + lc0 + 16 + i]
                 - ab[(1 * 48 + r) * PRP + lc0 + i - 1];
            hs2[(0 * 48 + r) * HSP + lc0 + i] = sav;
            hs2[(1 * 48 + r) * HSP + lc0 + i] = sbv;
        }
    }
    __syncthreads();

    if (t < 256) {
        int col = t & 31, seg = t >> 5;
        int rl0 = seg * 4;
        float sav = 0.f, sbv = 0.f;
#pragma unroll
        for (int k = 0; k < 17; k++) {
            sav += hs2[(0 * 48 + rl0 + k) * HSP + col];
            sbv += hs2[(1 * 48 + rl0 + k) * HSP + col];
        }
        int oc = C0 + col;
        int nx = min(W - 1, oc + 8) - max(0, oc - 8) + 1;

#pragma unroll
        for (int i = 0; i < 4; i++) {
            if (i > 0) {
                sav += hs2[(0 * 48 + rl0 + 16 + i) * HSP + col]
                     - hs2[(0 * 48 + rl0 + i - 1) * HSP + col];
                sbv += hs2[(1 * 48 + rl0 + 16 + i) * HSP + col]
                     - hs2[(1 * 48 + rl0 + i - 1) * HSP + col];
            }
            int orow = R0 + rl0 + i;
            int ny = min(H - 1, orow + 8) - max(0, orow - 8) + 1;
            float invN = __fdividef(1.0f, (float)(nx * ny));
            g_mab[pbase + orow * W + oc] = make_float2(sav * invN, sbv * invN);
        }
    }
}

// ---------- K4: upsample (PDL: hr loads pre-wait, float2 shared) ----------
__global__ __launch_bounds__(512)
void k_up(const float* __restrict__ hr, float* __restrict__ out) {
    __shared__ float2 sAB[4][257];
    int t = threadIdx.x;
    int plane = blockIdx.x >> 8;
    int g = blockIdx.x & 255;
    int Y0 = g * 4;
    int pb = plane * H * W;
    const float sc = 255.0f / 1023.0f;

    // pre-wait: front-load hr (independent of g_mab)
    int obase = plane * HH * WH + Y0 * WH;
    int i0 = t, i1 = t + 512;
    int r0 = i0 >> 8, x40 = i0 & 255;
    int r1 = i1 >> 8, x41 = i1 & 255;
    int ho0 = obase + r0 * WH + x40 * 4;
    int ho1 = obase + r1 * WH + x41 * 4;
    float4 h0 = *(const float4*)(hr + ho0);
    float4 h1 = *(const float4*)(hr + ho1);

    gdc_wait();                       // g_mab now visible

#pragma unroll
    for (int jj = 0; jj < 2; jj++) {
        int j = t + jj * 512;
        int r = j >> 8, col = j & 255;
        float yf = (Y0 + r) * sc;
        int y0 = (int)yf;
        int y1 = min(y0 + 1, H - 1);
        float wy = yf - (float)y0;
        float2 v0 = g_mab[pb + y0 * W + col];
        float2 v1 = g_mab[pb + y1 * W + col];
        float2 res = make_float2(v0.x + (v1.x - v0.x) * wy,
                                 v0.y + (v1.y - v0.y) * wy);
        sAB[r][col] = res;
        if (col == 255) sAB[r][256] = res;
    }
    __syncthreads();

#pragma unroll
    for (int jj = 0; jj < 2; jj++) {
        int r  = jj == 0 ? r0  : r1;
        int x4 = jj == 0 ? x40 : x41;
        int ho = jj == 0 ? ho0 : ho1;
        float4 h = jj == 0 ? h0 : h1;
        float4 o;
        float* hv = (float*)&h;
        float* ov = (float*)&o;
#pragma unroll
        for (int k = 0; k < 4; k++) {
            float xf = (x4 * 4 + k) * sc;
            int x0 = (int)xf;
            float wx = xf - (float)x0;
            float2 p0 = sAB[r][x0];
            float2 p1 = sAB[r][x0 + 1];
            float Av = p0.x + (p1.x - p0.x) * wx;
            float Bv = p0.y + (p1.y - p0.y) * wx;
            ov[k] = fmaf(Av, hv[k], Bv);
        }
        *(float4*)(out + ho) = o;
    }
}

extern "C" void kernel_launch(void* const* d_in, const int* in_sizes, int n_in,
                              void* d_out, int out_size) {
    const float* lr_x = (const float*)d_in[0];
    const float* lr_y = (const float*)d_in[1];
    const float* hr_x = (const float*)d_in[2];
    const float* l_a  = (const float*)d_in[3];
    float* out = (float*)d_out;

    static const int B1_SMEM = B1_FL * 4;    // 66240 B
    cudaFuncSetAttribute(k_box1, cudaFuncAttributeMaxDynamicSharedMemorySize,
                         B1_SMEM);

    cudaLaunchAttribute pdl[1];
    pdl[0].id = cudaLaunchAttributeProgrammaticStreamSerialization;
    pdl[0].val.programmaticStreamSerializationAllowed = 1;

    k_reduce1<<<768, 256>>>(l_a);

    {   // box1: PDL — overlaps its halo staging with reduce1
        cudaLaunchConfig_t cfg = {};
        cfg.gridDim = dim3(PLANES * 64);
        cfg.blockDim = dim3(384);
        cfg.dynamicSmemBytes = B1_SMEM;
        cfg.stream = 0;
        cfg.attrs = pdl;
        cfg.numAttrs = 1;
        cudaLaunchKernelEx(&cfg, k_box1, lr_x, lr_y, l_a);
    }

    {   // box2: PDL — launches during box1's tail, waits before reading g_ab
        cudaLaunchConfig_t cfg = {};
        cfg.gridDim = dim3(PLANES * 64);
        cfg.blockDim = dim3(384);
        cfg.dynamicSmemBytes = 0;
        cfg.stream = 0;
        cfg.attrs = pdl;
        cfg.numAttrs = 1;
        cudaLaunchKernelEx(&cfg, k_box2);
    }

    {   // k_up: PDL — overlaps its hr loads with box2
        cudaLaunchConfig_t cfg = {};
        cfg.gridDim = dim3(PLANES * 256);
        cfg.blockDim = dim3(512);
        cfg.dynamicSmemBytes = 0;
        cfg.stream = 0;
        cfg.attrs = pdl;
        cfg.numAttrs = 1;
        cudaLaunchKernelEx(&cfg, k_up, hr_x, out);
    }
}

// round 14
// speedup vs baseline: 1.0263x; 1.0263x over previous
#include <cuda_runtime.h>

constexpr int H = 256, W = 256, PLANES = 12;
constexpr int HH = 1024, WH = 1024;
constexpr float EPSF  = 1e-8f;
constexpr float EPSSF = 1e-12f;
constexpr int PSZ = PLANES * H * W;

constexpr int PRP = 49;   // halo pitch (48 + 1)
constexpr int HSP = 33;   // hsum pitch (32 + 1)

__device__ float  g_partial[768];
__device__ float2 g_ab [PSZ];    // interleaved (A, b)
__device__ float2 g_mab[PSZ];    // interleaved (meanA, meanb)

__device__ __forceinline__ void gdc_wait()    { asm volatile("griddepcontrol.wait;" ::: "memory"); }
__device__ __forceinline__ void gdc_trigger() { asm volatile("griddepcontrol.launch_dependents;" ::: "memory"); }

// ---------- K1: partial sums of |l_a|+eps ----------
__global__ void k_reduce1(const float* __restrict__ la) {
    __shared__ float sm[256];
    gdc_trigger();                    // let box1 stage its halo concurrently
    int t = threadIdx.x;
    float4 v = ((const float4*)la)[blockIdx.x * 256 + t];
    float s = fabsf(v.x) + fabsf(v.y) + fabsf(v.z) + fabsf(v.w) + 4.0f * EPSSF;
    sm[t] = s; __syncthreads();
    for (int off = 128; off > 0; off >>= 1) {
        if (t < off) sm[t] += sm[t + off];
        __syncthreads();
    }
    if (t == 0) g_partial[blockIdx.x] = sm[0];
}

// ---------- K2: box filter #1 + A,b (PDL: halo staged pre-wait) ----------
constexpr int B1_AXY = 3 * 48 * PRP;            // 7056 floats
constexpr int B1_FL  = B1_AXY + 6 * 48 * HSP;   // 16560 floats (66240 B)

__device__ __forceinline__ void acc_prod(float* s, float a, float x, float y,
                                         float sign) {
    float ax  = a * x;
    float a2x = ax * a;
    s[0] += sign * a;
    s[1] += sign * a2x * y;
    s[2] += sign * a2x;
    s[3] += sign * a * y;
    s[4] += sign * ax * ax;
    s[5] += sign * ax;
}

__global__ __launch_bounds__(384)
void k_box1(const float* __restrict__ lx,
            const float* __restrict__ ly,
            const float* __restrict__ la) {
    extern __shared__ float smd[];
    float* sa = smd;
    float* sx = smd + 48 * PRP;
    float* sy = smd + 2 * 48 * PRP;
    float* hs = smd + B1_AXY;        // [6][48][HSP]
    __shared__ float sred[256];
    __shared__ float s_inv;

    int t = threadIdx.x;
    int plane = blockIdx.x >> 6, tile = blockIdx.x & 63;
    int R0 = (tile >> 3) * 32;
    int C0 = (tile & 7) * 32;
    int pbase = plane * H * W;

    // phase 1 (pre-wait): stage 48x48 halo of a,x,y — independent of reduce1
    for (int i = t; i < 48 * 48; i += 384) {
        int lr = i / 48, lc = i - lr * 48;
        int gr = R0 - 8 + lr, gc = C0 - 8 + lc;
        float a = 0.f, x = 0.f, y = 0.f;
        if (gr >= 0 && gr < H && gc >= 0 && gc < W) {
            int idx = pbase + gr * W + gc;
            a = fabsf(la[idx]) + EPSSF;
            x = lx[idx];
            y = ly[idx];
        }
        int o = lr * PRP + lc;
        sa[o] = a; sx[o] = x; sy[o] = y;
    }

    gdc_wait();                       // reduce1's g_partial now visible

    if (t < 256)
        sred[t] = g_partial[t] + g_partial[t + 256] + g_partial[t + 512];
    __syncthreads();
    for (int off = 128; off > 0; off >>= 1) {
        if (t < off) sred[t] += sred[t + off];
        __syncthreads();
    }
    if (t == 0) s_inv = __fdividef(1.0f, sred[0]);
    __syncthreads();

    // phase 2: H-box with on-the-fly products. 384 jobs, 1 per thread.
    {
        int r = t >> 3, sg = t & 7;
        int base = r * PRP + sg * 4;
        float s[6] = {0,0,0,0,0,0};
#pragma unroll
        for (int k = 0; k < 17; k++)
            acc_prod(s, sa[base + k], sx[base + k], sy[base + k], 1.0f);
        int ho = r * HSP + sg * 4;
#pragma unroll
        for (int c = 0; c < 6; c++) hs[c * 48 * HSP + ho] = s[c];
#pragma unroll
        for (int i = 1; i < 4; i++) {
            int add = base + 16 + i, sub = base + i - 1;
            acc_prod(s, sa[add], sx[add], sy[add], 1.0f);
            acc_prod(s, sa[sub], sx[sub], sy[sub], -1.0f);
#pragma unroll
            for (int c = 0; c < 6; c++) hs[c * 48 * HSP + ho + i] = s[c];
        }
    }
    __syncthreads();

    // phase 3: V-box + A,b. 256 jobs (t < 256).
    if (t < 256) {
        float invS = s_inv;
        int col = t & 31, seg = t >> 5;
        int rl0 = seg * 4;
        float s[6] = {0,0,0,0,0,0};
#pragma unroll
        for (int k = 0; k < 17; k++) {
#pragma unroll
            for (int c = 0; c < 6; c++)
                s[c] += hs[(c * 48 + rl0 + k) * HSP + col];
        }
        int oc = C0 + col;
        int nx = min(W - 1, oc + 8) - max(0, oc - 8) + 1;

#pragma unroll
        for (int i = 0; i < 4; i++) {
            if (i > 0) {
#pragma unroll
                for (int c = 0; c < 6; c++)
                    s[c] += hs[(c * 48 + rl0 + 16 + i) * HSP + col]
                          - hs[(c * 48 + rl0 + i - 1) * HSP + col];
            }
            int orow = R0 + rl0 + i;
            int ny = min(H - 1, orow + 8) - max(0, orow - 8) + 1;
            float Nf = (float)(nx * ny);
            float invN = __fdividef(1.0f, Nf);

            float m_a    = s[0] * invN;
            float m_a2xy = s[1] * invN;
            float m_tax  = invS * s[2] * invN;
            float m_ay   = s[3] * invN;
            float m_a2x2 = s[4] * invN;
            float m_ax   = s[5] * invN;

            float temp = fabsf(m_a2x2 - Nf * m_tax * m_ax);
            float A = __fdividef(m_a2xy - Nf * m_tax * m_ay, temp + EPSF);
            float b = __fdividef(m_ay - A * m_ax, m_a);

            g_ab[pbase + orow * W + oc] = make_float2(A, b);
        }
    }
}

// ---------- K3: box filter #2 ----------
__global__ __launch_bounds__(384)
void k_box2() {
    __shared__ float ab [2 * 48 * PRP];
    __shared__ float hs2[2 * 48 * HSP];
    gdc_trigger();                    // let k_up front-load hr concurrently
    int t = threadIdx.x;
    int plane = blockIdx.x >> 6, tile = blockIdx.x & 63;
    int R0 = (tile >> 3) * 32;
    int C0 = (tile & 7) * 32;
    int pbase = plane * H * W;

    for (int i = t; i < 48 * 48; i += 384) {
        int lr = i / 48, lc = i - lr * 48;
        int gr = R0 - 8 + lr, gc = C0 - 8 + lc;
        float2 v = make_float2(0.f, 0.f);
        if (gr >= 0 && gr < H && gc >= 0 && gc < W)
            v = g_ab[pbase + gr * W + gc];
        ab[(0 * 48 + lr) * PRP + lc] = v.x;
        ab[(1 * 48 + lr) * PRP + lc] = v.y;
    }
    __syncthreads();

    {
        int r = t >> 3, sgc = t & 7;
        int lc0 = sgc * 4;
        float sav = 0.f, sbv = 0.f;
#pragma unroll
        for (int k = 0; k < 17; k++) {
            sav += ab[(0 * 48 + r) * PRP + lc0 + k];
            sbv += ab[(1 * 48 + r) * PRP + lc0 + k];
        }
        hs2[(0 * 48 + r) * HSP + lc0] = sav;
        hs2[(1 * 48 + r) * HSP + lc0] = sbv;
#pragma unroll
        for (int i = 1; i < 4; i++) {
            sav += ab[(0 * 48 + r) * PRP + lc0 + 16 + i]
                 - ab[(0 * 48 + r) * PRP + lc0 + i - 1];
            sbv += ab[(1 * 48 + r) * PRP + lc0 + 16 + i]
                 - ab[(1 * 48 + r) * PRP + lc0 + i - 1];
            hs2[(0 * 48 + r) * HSP + lc0 + i] = sav;
            hs2[(1 * 48 + r) * HSP + lc0 + i] = sbv;
        }
    }
    __syncthreads();

    if (t < 256) {
        int col = t & 31, seg = t >> 5;
        int rl0 = seg * 4;
        float sav = 0.f, sbv = 0.f;
#pragma unroll
        for (int k = 0; k < 17; k++) {
            sav += hs2[(0 * 48 + rl0 + k) * HSP + col];
            sbv += hs2[(1 * 48 + rl0 + k) * HSP + col];
        }
        int oc = C0 + col;
        int nx = min(W - 1, oc + 8) - max(0, oc - 8) + 1;

#pragma unroll
        for (int i = 0; i < 4; i++) {
            if (i > 0) {
                sav += hs2[(0 * 48 + rl0 + 16 + i) * HSP + col]
                     - hs2[(0 * 48 + rl0 + i - 1) * HSP + col];
                sbv += hs2[(1 * 48 + rl0 + 16 + i) * HSP + col]
                     - hs2[(1 * 48 + rl0 + i - 1) * HSP + col];
            }
            int orow = R0 + rl0 + i;
            int ny = min(H - 1, orow + 8) - max(0, orow - 8) + 1;
            float invN = __fdividef(1.0f, (float)(nx * ny));
            g_mab[pbase + orow * W + oc] = make_float2(sav * invN, sbv * invN);
        }
    }
}

// ---------- K4: upsample (PDL pre-load; select gather; forced 4 blocks/SM) ----------
__global__ __launch_bounds__(512, 4)
void k_up(const float* __restrict__ hr, float* __restrict__ out) {
    __shared__ float2 sAB[4][257];
    int t = threadIdx.x;
    int plane = blockIdx.x >> 8;
    int g = blockIdx.x & 255;
    int Y0 = g * 4;
    int pb = plane * H * W;
    const float sc = 255.0f / 1023.0f;

    // pre-wait: front-load hr (independent of g_mab)
    int obase = plane * HH * WH + Y0 * WH;
    int i0 = t, i1 = t + 512;
    int r0 = i0 >> 8, x40 = i0 & 255;
    int r1 = i1 >> 8, x41 = i1 & 255;
    int ho0 = obase + r0 * WH + x40 * 4;
    int ho1 = obase + r1 * WH + x41 * 4;
    float4 h0 = *(const float4*)(hr + ho0);
    float4 h1 = *(const float4*)(hr + ho1);

    gdc_wait();                       // g_mab now visible

#pragma unroll
    for (int jj = 0; jj < 2; jj++) {
        int j = t + jj * 512;
        int r = j >> 8, col = j & 255;
        float yf = (Y0 + r) * sc;
        int y0 = (int)yf;
        int y1 = min(y0 + 1, H - 1);
        float wy = yf - (float)y0;
        float2 v0 = g_mab[pb + y0 * W + col];
        float2 v1 = g_mab[pb + y1 * W + col];
        float2 res = make_float2(v0.x + (v1.x - v0.x) * wy,
                                 v0.y + (v1.y - v0.y) * wy);
        sAB[r][col] = res;
        if (col == 255) sAB[r][256] = res;
    }
    __syncthreads();

#pragma unroll
    for (int jj = 0; jj < 2; jj++) {
        int r  = jj == 0 ? r0  : r1;
        int x4 = jj == 0 ? x40 : x41;
        int ho = jj == 0 ? ho0 : ho1;
        float4 h = jj == 0 ? h0 : h1;
        int X0 = x4 * 4;
        int x0g = (int)((float)X0 * sc);
        float xv = (float)x0g;
        float2 p0 = sAB[r][x0g];
        float2 p1 = sAB[r][x0g + 1];
        float2 p2 = sAB[r][x0g + 2];

        float4 o;
        float* hv = (float*)&h;
        float* ov = (float*)&o;
#pragma unroll
        for (int k = 0; k < 4; k++) {
            float d = (float)(X0 + k) * sc - xv;
            bool st = d >= 1.0f;
            float wx = st ? d - 1.0f : d;
            float A0 = st ? p1.x : p0.x;
            float A1 = st ? p2.x : p1.x;
            float B0 = st ? p1.y : p0.y;
            float B1 = st ? p2.y : p1.y;
            float Av = A0 + (A1 - A0) * wx;
            float Bv = B0 + (B1 - B0) * wx;
            ov[k] = fmaf(Av, hv[k], Bv);
        }
        *(float4*)(out + ho) = o;
    }
}

extern "C" void kernel_launch(void* const* d_in, const int* in_sizes, int n_in,
                              void* d_out, int out_size) {
    const float* lr_x = (const float*)d_in[0];
    const float* lr_y = (const float*)d_in[1];
    const float* hr_x = (const float*)d_in[2];
    const float* l_a  = (const float*)d_in[3];
    float* out = (float*)d_out;

    static const int B1_SMEM = B1_FL * 4;    // 66240 B
    cudaFuncSetAttribute(k_box1, cudaFuncAttributeMaxDynamicSharedMemorySize,
                         B1_SMEM);

    cudaLaunchAttribute pdl[1];
    pdl[0].id = cudaLaunchAttributeProgrammaticStreamSerialization;
    pdl[0].val.programmaticStreamSerializationAllowed = 1;

    k_reduce1<<<768, 256>>>(l_a);

    {   // box1: PDL — overlaps its halo staging with reduce1
        cudaLaunchConfig_t cfg = {};
        cfg.gridDim = dim3(PLANES * 64);
        cfg.blockDim = dim3(384);
        cfg.dynamicSmemBytes = B1_SMEM;
        cfg.stream = 0;
        cfg.attrs = pdl;
        cfg.numAttrs = 1;
        cudaLaunchKernelEx(&cfg, k_box1, lr_x, lr_y, l_a);
    }

    k_box2<<<PLANES * 64, 384>>>();

    {   // k_up: PDL — overlaps its hr loads with box2
        cudaLaunchConfig_t cfg = {};
        cfg.gridDim = dim3(PLANES * 256);
        cfg.blockDim = dim3(512);
        cfg.dynamicSmemBytes = 0;
        cfg.stream = 0;
        cfg.attrs = pdl;
        cfg.numAttrs = 1;
        cudaLaunchKernelEx(&cfg, k_up, hr_x, out);
    }
}